// round 3
// baseline (speedup 1.0000x reference)
#include <cuda_runtime.h>

#define HH 2048
#define WW 2048
#define NB 148
#define NT 1024
#define NW (NT/32)

// Scratch (device globals; no allocation allowed)
__device__ float4 g_bpart[4][NB];        // [2],[3]: phase0 ch9/ch10; [0],[1]: band double-buffer
__device__ unsigned int g_arrive = 0;    // monotone across replays
__device__ unsigned int g_release = 0;   // monotone across replays

__device__ __forceinline__ float neg_inf() { return __int_as_float(0xff800000); }

// logsumexp-style merge of (max, sum, sum_x, sum_y)
__device__ __forceinline__ void merge4(float &M, float &S, float &Sx, float &Sy,
                                       float m2, float s2, float sx2, float sy2) {
    float nm = fmaxf(M, m2);
    if (nm == neg_inf()) return;  // both empty
    float a = expf(M - nm);
    float b = expf(m2 - nm);
    S  = S  * a + s2  * b;
    Sx = Sx * a + sx2 * b;
    Sy = Sy * a + sy2 * b;
    M = nm;
}

// Block-wide merge reduce; result valid on thread 0.
__device__ void block_merge(float &M, float &S, float &Sx, float &Sy) {
    __shared__ float bm[NW][4];
    int tid = threadIdx.x, lane = tid & 31, w = tid >> 5;
    #pragma unroll
    for (int o = 16; o; o >>= 1) {
        float m2 = __shfl_down_sync(0xffffffffu, M, o);
        float s2 = __shfl_down_sync(0xffffffffu, S, o);
        float x2 = __shfl_down_sync(0xffffffffu, Sx, o);
        float y2 = __shfl_down_sync(0xffffffffu, Sy, o);
        merge4(M, S, Sx, Sy, m2, s2, x2, y2);
    }
    __syncthreads();   // guards bm reuse across consecutive calls
    if (lane == 0) { bm[w][0] = M; bm[w][1] = S; bm[w][2] = Sx; bm[w][3] = Sy; }
    __syncthreads();
    if (tid == 0) {
        #pragma unroll
        for (int k = 1; k < NW; k++)
            merge4(M, S, Sx, Sy, bm[k][0], bm[k][1], bm[k][2], bm[k][3]);
    }
}

// Online softmax accumulate in RAW domain. thr caches (M-88)/100 so the
// steady-state cost per element is one compare. Dropped terms < ~e^-88.
__device__ __forceinline__ void accr(float &M, float &S, float &Sx, float &Sy, float &thr,
                                     float raw, float x, float y) {
    if (raw > thr) {
        float v = raw * 100.f;
        if (v > M) {
            float r = expf(M - v);   // expf(-inf)=0 handles first element
            S  = S  * r + 1.f;
            Sx = Sx * r + x;
            Sy = Sy * r + y;
            M = v;
            thr = (M - 88.f) * 0.01f;
        } else {
            float e = expf(v - M);
            S += e; Sx += x * e; Sy += y * e;
        }
    }
}

// Grid barrier: monotone counters, no resets -> graph-replay safe.
// Invariant at every launch start: g_arrive == g_release * NB.
__device__ __forceinline__ void gsync(unsigned &epoch, unsigned base) {
    __threadfence();
    __syncthreads();
    if (threadIdx.x == 0) {
        epoch++;
        unsigned target = base + epoch;          // releases after this barrier
        unsigned t = atomicAdd(&g_arrive, 1u);
        if (t == target * NB - 1u) {
            __threadfence();
            atomicAdd(&g_release, 1u);
        } else {
            while (*((volatile unsigned*)&g_release) < target) { __nanosleep(32); }
        }
    }
    __syncthreads();
    __threadfence();
}

__device__ __forceinline__ void acc4(float &M, float &S, float &Sx, float &Sy, float &thr,
                                     float4 A, int idx) {
    float y  = (float)(idx >> 9);
    float x0 = (float)((idx & 511) << 2);
    accr(M, S, Sx, Sy, thr, A.x, x0,       y);
    accr(M, S, Sx, Sy, thr, A.y, x0 + 1.f, y);
    accr(M, S, Sx, Sy, thr, A.z, x0 + 2.f, y);
    accr(M, S, Sx, Sy, thr, A.w, x0 + 3.f, y);
}

__global__ void __launch_bounds__(NT, 1)
sa_kernel(const float * __restrict__ hm, float * __restrict__ out) {
    const int b = blockIdx.x;
    const int tid = threadIdx.x;
    __shared__ unsigned s_base;
    __shared__ int s_r0, s_r1;
    __shared__ float s_ay;
    __shared__ float s_ay2[2];

    if (tid == 0) s_base = *((volatile unsigned*)&g_release);
    __syncthreads();
    const unsigned base = s_base;
    unsigned epoch = 0;

    // ---------------- Phase 0: full soft-argmax of channels 9 & 10 ----------------
    {
        int c  = (b < 74) ? 0 : 1;
        int bb = (b < 74) ? b : b - 74;
        const float4 *p4 = reinterpret_cast<const float4*>(hm + (size_t)(9 + c) * HH * WW);
        float M = neg_inf(), S = 0.f, Sx = 0.f, Sy = 0.f, thr = neg_inf();
        const int total  = HH * (WW / 4);   // 1,048,576 float4
        const int stride = 74 * NT;         // 75,776
        int idx = bb * NT + tid;
        // main loop: 4 independent LDG.128 in flight before processing
        for (; idx + 3 * stride < total; idx += 4 * stride) {
            float4 A = p4[idx];
            float4 B = p4[idx + stride];
            float4 C = p4[idx + 2 * stride];
            float4 D = p4[idx + 3 * stride];
            acc4(M, S, Sx, Sy, thr, A, idx);
            acc4(M, S, Sx, Sy, thr, B, idx + stride);
            acc4(M, S, Sx, Sy, thr, C, idx + 2 * stride);
            acc4(M, S, Sx, Sy, thr, D, idx + 3 * stride);
        }
        for (; idx < total; idx += stride) {
            float4 A = p4[idx];
            acc4(M, S, Sx, Sy, thr, A, idx);
        }
        block_merge(M, S, Sx, Sy);
        if (tid == 0) g_bpart[2 + c][bb] = make_float4(M, S, Sx, Sy);
    }
    gsync(epoch, base);

    // ---------- Phase 0 finisher: every block reduces redundantly (identical results) ----------
    float yA, yB;                    // y_{i+1}, y_{i+2}
    float dis, dsum = 0.f, dnum = 0.f;
    for (int c = 0; c < 2; c++) {
        float M = neg_inf(), S = 0.f, Sx = 0.f, Sy = 0.f;
        if (tid < 74) { float4 p = g_bpart[2 + c][tid]; M = p.x; S = p.y; Sx = p.z; Sy = p.w; }
        block_merge(M, S, Sx, Sy);
        if (tid == 0) {
            float ax = Sx / S, ay = Sy / S;
            s_ay2[c] = ay;
            if (b == 0) { out[(9 + c) * 2 + 0] = ax; out[(9 + c) * 2 + 1] = ay; }
        }
        __syncthreads();
    }
    yA = s_ay2[0];                   // y9
    yB = s_ay2[1];                   // y10
    dis = __fsub_rn(yB, yA);         // dis0

    // ---------------- Band phases i = 8 .. 0 (one grid barrier each) ----------------
    for (int i = 8; i >= 0; i--) {
        if (tid == 0) {
            // scalar band logic; __f*_rn blocks FMA contraction to match reference
            float y1 = yA, y2 = yB;
            float last_y = floorf(y1);
            float tmp = ceilf(__fsub_rn(y2, y1));
            if (fabsf(__fsub_rn(tmp, dis)) > __fmul_rn(0.35f, dis)) {
                dsum = __fadd_rn(dsum, tmp);
                dnum = __fadd_rn(dnum, 1.0f);
                dis  = __fdiv_rn(dsum, fmaxf(dnum, 1.0f));
            }
            float t  = __fmul_rn(1.8f, dis);
            float sr = __fsub_rn(last_y, t);
            float end_y   = rintf(__fadd_rn(sr, t));   // round-half-even = jnp.round
            float start_y = rintf(sr);
            s_r0 = (start_y <= 0.f) ? 0  : (start_y >= (float)HH       ? HH     : (int)start_y);
            s_r1 = (end_y   <  0.f) ? -1 : (end_y   >= (float)(HH - 1) ? HH - 1 : (int)end_y);
        }
        __syncthreads();
        const int r0 = s_r0, r1 = s_r1;

        float M = neg_inf(), S = 0.f, Sx = 0.f, Sy = 0.f, thr = neg_inf();
        // 512 float4 per row; threads 0..511 each load one
        for (int row = r0 + b; row <= r1; row += NB) {
            if (tid < 512) {
                const float4 *rp = reinterpret_cast<const float4*>(hm + ((size_t)i * HH + row) * WW);
                float4 A = rp[tid];
                float yv = (float)row;
                float x0 = (float)(tid << 2);
                accr(M, S, Sx, Sy, thr, A.x, x0,       yv);
                accr(M, S, Sx, Sy, thr, A.y, x0 + 1.f, yv);
                accr(M, S, Sx, Sy, thr, A.z, x0 + 2.f, yv);
                accr(M, S, Sx, Sy, thr, A.w, x0 + 3.f, yv);
            }
        }
        const int bi = (8 - i) & 1;   // double-buffer by band parity
        block_merge(M, S, Sx, Sy);
        if (tid == 0) g_bpart[bi][b] = make_float4(M, S, Sx, Sy);
        gsync(epoch, base);

        // finisher (redundant in every block): band rows + closed-form out-of-band term
        M = neg_inf(); S = 0.f; Sx = 0.f; Sy = 0.f;
        if (tid < NB) { float4 p = g_bpart[bi][tid]; M = p.x; S = p.y; Sx = p.z; Sy = p.w; }
        block_merge(M, S, Sx, Sy);
        if (tid == 0) {
            float Rn = (r1 >= r0) ? (float)(r1 - r0 + 1) : 0.f;
            float mb = M;
            float m;
            if (Rn >= 2048.f)      m = mb;               // band covers everything
            else if (Rn > 0.f)     m = fmaxf(mb, 0.f);   // zeros exist outside band
            else                   m = 0.f;              // empty band: all-zero map
            float sc = (Rn > 0.f) ? expf(mb - m) : 0.f;
            S *= sc; Sx *= sc; Sy *= sc;

            if (Rn < 2048.f) {
                const float NTOT  = 4194304.f;      // H*W
                const float SXROW = 2096128.f;      // W*(W-1)/2
                const float SXTOT = 4292870144.f;   // H * SXROW
                const float SYTOT = 4292870144.f;   // W * H*(H-1)/2
                float e0 = expf(-m);
                S  += (NTOT  - Rn * 2048.f) * e0;
                Sx += (SXTOT - Rn * SXROW ) * e0;
                Sy += (SYTOT - 2048.f * (0.5f * (float)(r0 + r1) * Rn)) * e0;
            }
            float ax = Sx / S, ay = Sy / S;
            s_ay = ay;
            if (b == 0) { out[i * 2 + 0] = ax; out[i * 2 + 1] = ay; }
        }
        __syncthreads();
        yB = yA;
        yA = s_ay;
    }
}

extern "C" void kernel_launch(void* const* d_in, const int* in_sizes, int n_in,
                              void* d_out, int out_size) {
    const float *hm = (const float*)d_in[0];
    float *out = (float*)d_out;
    (void)in_sizes; (void)n_in; (void)out_size;

    sa_kernel<<<NB, NT>>>(hm, out);
}

// round 5
// speedup vs baseline: 1.1100x; 1.1100x over previous
#include <cuda_runtime.h>

#define HH 2048
#define WW 2048
#define NB 148
#define NT 1024
#define NW (NT/32)
#define CBLK 74
#define TOT4 (HH*WW/4)          // 1,048,576 float4 per channel
#define STR (CBLK*NT)           // 75,776

// Scratch (device globals; no allocation allowed)
// slots 0,1: band double-buffer; 2,3: pass1 raw maxima ch9/ch10; 4,5: pass2 sums ch9/ch10
__device__ float4 g_bpart[6][NB];
__device__ unsigned int g_arrive = 0;    // monotone across replays
__device__ unsigned int g_release = 0;   // monotone across replays

__device__ __forceinline__ float neg_inf() { return __int_as_float(0xff800000); }

// logsumexp-style merge of (max, sum, sum_x, sum_y)
__device__ __forceinline__ void merge4(float &M, float &S, float &Sx, float &Sy,
                                       float m2, float s2, float sx2, float sy2) {
    float nm = fmaxf(M, m2);
    if (nm == neg_inf()) return;
    float a = expf(M - nm);
    float b = expf(m2 - nm);
    S  = S  * a + s2  * b;
    Sx = Sx * a + sx2 * b;
    Sy = Sy * a + sy2 * b;
    M = nm;
}

// Block-wide merge reduce; result valid on thread 0.
__device__ void block_merge(float &M, float &S, float &Sx, float &Sy) {
    __shared__ float bm[NW][4];
    int tid = threadIdx.x, lane = tid & 31, w = tid >> 5;
    #pragma unroll
    for (int o = 16; o; o >>= 1) {
        float m2 = __shfl_down_sync(0xffffffffu, M, o);
        float s2 = __shfl_down_sync(0xffffffffu, S, o);
        float x2 = __shfl_down_sync(0xffffffffu, Sx, o);
        float y2 = __shfl_down_sync(0xffffffffu, Sy, o);
        merge4(M, S, Sx, Sy, m2, s2, x2, y2);
    }
    __syncthreads();
    if (lane == 0) { bm[w][0] = M; bm[w][1] = S; bm[w][2] = Sx; bm[w][3] = Sy; }
    __syncthreads();
    if (tid == 0) {
        #pragma unroll
        for (int k = 1; k < NW; k++)
            merge4(M, S, Sx, Sy, bm[k][0], bm[k][1], bm[k][2], bm[k][3]);
    }
}

// Block-wide max; result valid on thread 0.
__device__ float block_max(float m) {
    __shared__ float sm[NW];
    int tid = threadIdx.x;
    #pragma unroll
    for (int o = 16; o; o >>= 1) m = fmaxf(m, __shfl_xor_sync(0xffffffffu, m, o));
    __syncthreads();
    if ((tid & 31) == 0) sm[tid >> 5] = m;
    __syncthreads();
    if (tid == 0) {
        #pragma unroll
        for (int k = 1; k < NW; k++) m = fmaxf(m, sm[k]);
    }
    return m;
}

// Block-wide 3-way sum; results valid on thread 0.
__device__ void block_sum3(float &S, float &Sx, float &Sy) {
    __shared__ float ss[NW][3];
    int tid = threadIdx.x;
    #pragma unroll
    for (int o = 16; o; o >>= 1) {
        S  += __shfl_xor_sync(0xffffffffu, S, o);
        Sx += __shfl_xor_sync(0xffffffffu, Sx, o);
        Sy += __shfl_xor_sync(0xffffffffu, Sy, o);
    }
    __syncthreads();
    if ((tid & 31) == 0) { ss[tid >> 5][0] = S; ss[tid >> 5][1] = Sx; ss[tid >> 5][2] = Sy; }
    __syncthreads();
    if (tid == 0) {
        #pragma unroll
        for (int k = 1; k < NW; k++) { S += ss[k][0]; Sx += ss[k][1]; Sy += ss[k][2]; }
    }
}

// Online softmax accumulate (band phases only; tiny workload there).
__device__ __forceinline__ void accr(float &M, float &S, float &Sx, float &Sy, float &thr,
                                     float raw, float x, float y) {
    if (raw > thr) {
        float v = raw * 100.f;
        if (v > M) {
            float r = expf(M - v);
            S  = S  * r + 1.f;
            Sx = Sx * r + x;
            Sy = Sy * r + y;
            M = v;
            thr = (M - 88.f) * 0.01f;
        } else {
            float e = expf(v - M);
            S += e; Sx += x * e; Sy += y * e;
        }
    }
}

// Fixed-max accumulate for pass 2 slow path. Ms is the SCALED (x100) global max.
__device__ __forceinline__ void accf(float Ms, float &S, float &Sx, float &Sy,
                                     float raw, float x, float y) {
    float v = raw * 100.f;
    if (v > Ms - 88.f) {
        float e = expf(v - Ms);
        S += e; Sx += x * e; Sy += y * e;
    }
}

// Grid barrier: monotone counters, no resets -> graph-replay safe.
__device__ __forceinline__ void gsync(unsigned &epoch, unsigned base) {
    __threadfence();
    __syncthreads();
    if (threadIdx.x == 0) {
        epoch++;
        unsigned target = base + epoch;
        unsigned t = atomicAdd(&g_arrive, 1u);
        if (t == target * NB - 1u) {
            __threadfence();
            atomicAdd(&g_release, 1u);
        } else {
            while (*((volatile unsigned*)&g_release) < target) { __nanosleep(32); }
        }
    }
    __syncthreads();
    __threadfence();
}

__device__ __forceinline__ float fmax4(float4 A) {
    return fmaxf(fmaxf(A.x, A.y), fmaxf(A.z, A.w));
}

__global__ void __launch_bounds__(NT, 1)
sa_kernel(const float * __restrict__ hm, float * __restrict__ out) {
    const int b = blockIdx.x;
    const int tid = threadIdx.x;
    __shared__ unsigned s_base;
    __shared__ int s_r0, s_r1;
    __shared__ float s_ay;
    __shared__ float s_ay2[2];
    __shared__ float s_M[2];

    if (tid == 0) s_base = *((volatile unsigned*)&g_release);
    __syncthreads();
    const unsigned base = s_base;
    unsigned epoch = 0;

    const int c  = (b < CBLK) ? 0 : 1;
    const int bb = (b < CBLK) ? b : b - CBLK;
    const float4 *p4 = reinterpret_cast<const float4*>(hm + (size_t)(9 + c) * HH * WW);
    const int ibase = bb * NT + tid;

    // ------------- Phase 0 / pass 1: branch-free RAW max, tile maxima kept in regs -------------
    // tiles: bmx[0]:t0-3  bmx[1]:t4-7  bmx[2]:t8-11  bmx[3]:t12-13 (t13 predicated)
    float bmx[4];
    {
        #pragma unroll
        for (int k = 0; k < 3; k++) {
            float4 A = p4[ibase + (4*k + 0) * STR];
            float4 B = p4[ibase + (4*k + 1) * STR];
            float4 C = p4[ibase + (4*k + 2) * STR];
            float4 D = p4[ibase + (4*k + 3) * STR];
            bmx[k] = fmaxf(fmaxf(fmax4(A), fmax4(B)), fmaxf(fmax4(C), fmax4(D)));
        }
        float4 A = p4[ibase + 12 * STR];
        float m3 = fmax4(A);
        int i13 = ibase + 13 * STR;
        if (i13 < TOT4) { float4 B = p4[i13]; m3 = fmaxf(m3, fmax4(B)); }
        bmx[3] = m3;
        float m = block_max(fmaxf(fmaxf(bmx[0], bmx[1]), fmaxf(bmx[2], bmx[3])));
        if (tid == 0) g_bpart[2 + c][bb] = make_float4(m, 0.f, 0.f, 0.f);  // RAW max
    }
    gsync(epoch, base);

    // Every block computes both channels' RAW global maxima (identical everywhere).
    for (int cc = 0; cc < 2; cc++) {
        float m = (tid < CBLK) ? g_bpart[2 + cc][tid].x : neg_inf();
        m = block_max(m);
        if (tid == 0) s_M[cc] = m;
    }
    __syncthreads();

    // ---------- Phase 0 / pass 2: ballot-skip resum (L2 hits on the rare reloads) ----------
    {
        const float Mraw   = s_M[c];
        const float Ms     = Mraw * 100.f;      // scaled max used in exp
        const float thrRaw = Mraw - 0.88f;      // raw-domain skip threshold (= (Ms-88)/100)
        float S = 0.f, Sx = 0.f, Sy = 0.f;
        #pragma unroll
        for (int k = 0; k < 4; k++) {
            if (__any_sync(0xffffffffu, bmx[k] > thrRaw)) {
                int tlo = 4 * k, thi = (k == 3) ? 14 : 4 * k + 4;
                for (int t = tlo; t < thi; t++) {
                    int idx = ibase + t * STR;
                    if (idx < TOT4) {
                        float4 A = p4[idx];
                        float y  = (float)(idx >> 9);
                        float x0 = (float)((idx & 511) << 2);
                        accf(Ms, S, Sx, Sy, A.x, x0,       y);
                        accf(Ms, S, Sx, Sy, A.y, x0 + 1.f, y);
                        accf(Ms, S, Sx, Sy, A.z, x0 + 2.f, y);
                        accf(Ms, S, Sx, Sy, A.w, x0 + 3.f, y);
                    }
                }
            }
        }
        block_sum3(S, Sx, Sy);
        if (tid == 0) g_bpart[4 + c][bb] = make_float4(S, Sx, Sy, 0.f);
    }
    gsync(epoch, base);

    // ---------- Phase 0 finisher: every block reduces redundantly (identical results) ----------
    float yA, yB;
    float dis, dsum = 0.f, dnum = 0.f;
    for (int cc = 0; cc < 2; cc++) {
        float S = 0.f, Sx = 0.f, Sy = 0.f;
        if (tid < CBLK) { float4 p = g_bpart[4 + cc][tid]; S = p.x; Sx = p.y; Sy = p.z; }
        block_sum3(S, Sx, Sy);
        if (tid == 0) {
            float ax = Sx / S, ay = Sy / S;
            s_ay2[cc] = ay;
            if (b == 0) { out[(9 + cc) * 2 + 0] = ax; out[(9 + cc) * 2 + 1] = ay; }
        }
        __syncthreads();
    }
    yA = s_ay2[0];                   // y9
    yB = s_ay2[1];                   // y10
    dis = __fsub_rn(yB, yA);         // dis0

    // ---------------- Band phases i = 8 .. 0 (one grid barrier each) ----------------
    for (int i = 8; i >= 0; i--) {
        if (tid == 0) {
            // scalar band logic; __f*_rn blocks FMA contraction to match reference
            float y1 = yA, y2 = yB;
            float last_y = floorf(y1);
            float tmp = ceilf(__fsub_rn(y2, y1));
            if (fabsf(__fsub_rn(tmp, dis)) > __fmul_rn(0.35f, dis)) {
                dsum = __fadd_rn(dsum, tmp);
                dnum = __fadd_rn(dnum, 1.0f);
                dis  = __fdiv_rn(dsum, fmaxf(dnum, 1.0f));
            }
            float t  = __fmul_rn(1.8f, dis);
            float sr = __fsub_rn(last_y, t);
            float end_y   = rintf(__fadd_rn(sr, t));   // round-half-even = jnp.round
            float start_y = rintf(sr);
            s_r0 = (start_y <= 0.f) ? 0  : (start_y >= (float)HH       ? HH     : (int)start_y);
            s_r1 = (end_y   <  0.f) ? -1 : (end_y   >= (float)(HH - 1) ? HH - 1 : (int)end_y);
        }
        __syncthreads();
        const int r0 = s_r0, r1 = s_r1;

        float M = neg_inf(), S = 0.f, Sx = 0.f, Sy = 0.f, thr = neg_inf();
        for (int row = r0 + b; row <= r1; row += NB) {
            if (tid < 512) {
                const float4 *rp = reinterpret_cast<const float4*>(hm + ((size_t)i * HH + row) * WW);
                float4 A = rp[tid];
                float yv = (float)row;
                float x0 = (float)(tid << 2);
                accr(M, S, Sx, Sy, thr, A.x, x0,       yv);
                accr(M, S, Sx, Sy, thr, A.y, x0 + 1.f, yv);
                accr(M, S, Sx, Sy, thr, A.z, x0 + 2.f, yv);
                accr(M, S, Sx, Sy, thr, A.w, x0 + 3.f, yv);
            }
        }
        const int bi = (8 - i) & 1;   // double-buffer by band parity
        block_merge(M, S, Sx, Sy);
        if (tid == 0) g_bpart[bi][b] = make_float4(M, S, Sx, Sy);
        gsync(epoch, base);

        // finisher (redundant in every block): band rows + closed-form out-of-band term
        M = neg_inf(); S = 0.f; Sx = 0.f; Sy = 0.f;
        if (tid < NB) { float4 p = g_bpart[bi][tid]; M = p.x; S = p.y; Sx = p.z; Sy = p.w; }
        block_merge(M, S, Sx, Sy);
        if (tid == 0) {
            float Rn = (r1 >= r0) ? (float)(r1 - r0 + 1) : 0.f;
            float mb = M;
            float m;
            if (Rn >= 2048.f)      m = mb;
            else if (Rn > 0.f)     m = fmaxf(mb, 0.f);
            else                   m = 0.f;
            float sc = (Rn > 0.f) ? expf(mb - m) : 0.f;
            S *= sc; Sx *= sc; Sy *= sc;

            if (Rn < 2048.f) {
                const float NTOT  = 4194304.f;      // H*W
                const float SXROW = 2096128.f;      // W*(W-1)/2
                const float SXTOT = 4292870144.f;   // H * SXROW
                const float SYTOT = 4292870144.f;   // W * H*(H-1)/2
                float e0 = expf(-m);
                S  += (NTOT  - Rn * 2048.f) * e0;
                Sx += (SXTOT - Rn * SXROW ) * e0;
                Sy += (SYTOT - 2048.f * (0.5f * (float)(r0 + r1) * Rn)) * e0;
            }
            float ax = Sx / S, ay = Sy / S;
            s_ay = ay;
            if (b == 0) { out[i * 2 + 0] = ax; out[i * 2 + 1] = ay; }
        }
        __syncthreads();
        yB = yA;
        yA = s_ay;
    }
}

extern "C" void kernel_launch(void* const* d_in, const int* in_sizes, int n_in,
                              void* d_out, int out_size) {
    const float *hm = (const float*)d_in[0];
    float *out = (float*)d_out;
    (void)in_sizes; (void)n_in; (void)out_size;

    sa_kernel<<<NB, NT>>>(hm, out);
}

// round 6
// speedup vs baseline: 1.4338x; 1.2917x over previous
#include <cuda_runtime.h>

#define HH 2048
#define WW 2048
#define NB 148
#define NT 1024
#define NW (NT/32)
#define CBLK 74
#define TOT4 (HH*WW/4)          // 1,048,576 float4 per channel
#define STR (CBLK*NT)           // 75,776

// Scratch (device globals; no allocation allowed)
// slots 0,1: band double-buffer; 2,3: pass1 raw maxima ch9/ch10; 4,5: pass2 sums ch9/ch10
__device__ float4 g_bpart[6][NB];
__device__ unsigned g_flag[NB];          // per-block arrival epochs (monotone)
__device__ unsigned g_rel = 0;           // release epoch (monotone)

__device__ __forceinline__ float neg_inf() { return __int_as_float(0xff800000); }

// Block-wide max, broadcast to ALL threads.
__device__ float block_max_bcast(float m) {
    __shared__ float sm[NW];
    __shared__ float sM;
    int tid = threadIdx.x;
    __syncthreads();                       // protect smem reuse across calls
    #pragma unroll
    for (int o = 16; o; o >>= 1) m = fmaxf(m, __shfl_xor_sync(0xffffffffu, m, o));
    if ((tid & 31) == 0) sm[tid >> 5] = m;
    __syncthreads();
    if (tid < 32) {                        // NW == 32 exactly
        float t = sm[tid];
        #pragma unroll
        for (int o = 16; o; o >>= 1) t = fmaxf(t, __shfl_xor_sync(0xffffffffu, t, o));
        if (tid == 0) sM = t;
    }
    __syncthreads();
    return sM;
}

// Block-wide 3-way sum; result valid on thread 0. Warp-parallel final fold.
__device__ void block_sum3(float &S, float &Sx, float &Sy) {
    __shared__ float ss[NW][3];
    int tid = threadIdx.x;
    __syncthreads();                       // protect smem reuse across calls
    #pragma unroll
    for (int o = 16; o; o >>= 1) {
        S  += __shfl_xor_sync(0xffffffffu, S, o);
        Sx += __shfl_xor_sync(0xffffffffu, Sx, o);
        Sy += __shfl_xor_sync(0xffffffffu, Sy, o);
    }
    if ((tid & 31) == 0) { ss[tid >> 5][0] = S; ss[tid >> 5][1] = Sx; ss[tid >> 5][2] = Sy; }
    __syncthreads();
    if (tid < 32) {
        S = ss[tid][0]; Sx = ss[tid][1]; Sy = ss[tid][2];
        #pragma unroll
        for (int o = 16; o; o >>= 1) {
            S  += __shfl_xor_sync(0xffffffffu, S, o);
            Sx += __shfl_xor_sync(0xffffffffu, Sx, o);
            Sy += __shfl_xor_sync(0xffffffffu, Sy, o);
        }
    }
}

// Fixed-max accumulate for phase0 pass 2. Ms is the SCALED (x100) global max.
__device__ __forceinline__ void accf(float Ms, float &S, float &Sx, float &Sy,
                                     float raw, float x, float y) {
    float v = raw * 100.f;
    if (v > Ms - 88.f) {
        float e = expf(v - Ms);
        S += e; Sx += x * e; Sy += y * e;
    }
}

// Grid barrier: per-block flag stores + block-0 parallel aggregation. No atomics,
// no nanosleep. Monotone epochs -> graph-replay safe (invariant at launch start:
// g_flag[b] == g_rel for all b).
__device__ __forceinline__ void gsync(unsigned &epoch, unsigned base) {
    const int b = blockIdx.x;
    const int tid = threadIdx.x;
    __threadfence();
    __syncthreads();
    epoch++;
    const unsigned target = base + epoch;
    if (b == 0) {
        if (tid == 0) *(volatile unsigned*)&g_flag[0] = target;
        if (tid < NB) {
            while (*(volatile unsigned*)&g_flag[tid] < target) {}
        }
        __syncthreads();
        if (tid == 0) { __threadfence(); *(volatile unsigned*)&g_rel = target; }
    } else {
        if (tid == 0) {
            *(volatile unsigned*)&g_flag[b] = target;
            while (*(volatile unsigned*)&g_rel < target) {}
        }
        __syncthreads();
    }
    __threadfence();
}

__device__ __forceinline__ float fmax4(float4 A) {
    return fmaxf(fmaxf(A.x, A.y), fmaxf(A.z, A.w));
}

__global__ void __launch_bounds__(NT, 1)
sa_kernel(const float * __restrict__ hm, float * __restrict__ out) {
    const int b = blockIdx.x;
    const int tid = threadIdx.x;
    __shared__ unsigned s_base;
    __shared__ int s_r0, s_r1;
    __shared__ float s_ay;
    __shared__ float s_ay2[2];

    if (tid == 0) s_base = *((volatile unsigned*)&g_rel);
    __syncthreads();
    const unsigned base = s_base;
    unsigned epoch = 0;

    const int c  = (b < CBLK) ? 0 : 1;
    const int bb = (b < CBLK) ? b : b - CBLK;
    const float4 *p4 = reinterpret_cast<const float4*>(hm + (size_t)(9 + c) * HH * WW);
    const int ibase = bb * NT + tid;

    // ------------- Phase 0 / pass 1: branch-free RAW max, tile maxima kept in regs -------------
    // tiles: bmx[0]:t0-3  bmx[1]:t4-7  bmx[2]:t8-11  bmx[3]:t12-13 (t13 predicated)
    float bmx[4];
    {
        #pragma unroll
        for (int k = 0; k < 3; k++) {
            float4 A = p4[ibase + (4*k + 0) * STR];
            float4 B = p4[ibase + (4*k + 1) * STR];
            float4 C = p4[ibase + (4*k + 2) * STR];
            float4 D = p4[ibase + (4*k + 3) * STR];
            bmx[k] = fmaxf(fmaxf(fmax4(A), fmax4(B)), fmaxf(fmax4(C), fmax4(D)));
        }
        float4 A = p4[ibase + 12 * STR];
        float m3 = fmax4(A);
        int i13 = ibase + 13 * STR;
        if (i13 < TOT4) { float4 B = p4[i13]; m3 = fmaxf(m3, fmax4(B)); }
        bmx[3] = m3;
        float m = block_max_bcast(fmaxf(fmaxf(bmx[0], bmx[1]), fmaxf(bmx[2], bmx[3])));
        if (tid == 0) g_bpart[2 + c][bb] = make_float4(m, 0.f, 0.f, 0.f);  // RAW max
    }
    gsync(epoch, base);

    // This block's channel RAW global max (identical in all blocks of same channel).
    float Mraw;
    {
        float m = (tid < CBLK) ? g_bpart[2 + c][tid].x : neg_inf();
        Mraw = block_max_bcast(m);
    }

    // ---------- Phase 0 / pass 2: ballot-skip resum (L2 hits on the rare reloads) ----------
    {
        const float Ms     = Mraw * 100.f;      // scaled max used in exp
        const float thrRaw = Mraw - 0.88f;      // raw-domain skip threshold
        float S = 0.f, Sx = 0.f, Sy = 0.f;
        #pragma unroll
        for (int k = 0; k < 4; k++) {
            if (__any_sync(0xffffffffu, bmx[k] > thrRaw)) {
                int tlo = 4 * k, thi = (k == 3) ? 14 : 4 * k + 4;
                for (int t = tlo; t < thi; t++) {
                    int idx = ibase + t * STR;
                    if (idx < TOT4) {
                        float4 A = p4[idx];
                        float y  = (float)(idx >> 9);
                        float x0 = (float)((idx & 511) << 2);
                        accf(Ms, S, Sx, Sy, A.x, x0,       y);
                        accf(Ms, S, Sx, Sy, A.y, x0 + 1.f, y);
                        accf(Ms, S, Sx, Sy, A.z, x0 + 2.f, y);
                        accf(Ms, S, Sx, Sy, A.w, x0 + 3.f, y);
                    }
                }
            }
        }
        block_sum3(S, Sx, Sy);
        if (tid == 0) g_bpart[4 + c][bb] = make_float4(S, Sx, Sy, 0.f);
    }
    gsync(epoch, base);

    // ---------- Phase 0 finisher: every block reduces redundantly (identical results) ----------
    float yA, yB;
    float dis, dsum = 0.f, dnum = 0.f;
    for (int cc = 0; cc < 2; cc++) {
        float S = 0.f, Sx = 0.f, Sy = 0.f;
        if (tid < CBLK) { float4 p = g_bpart[4 + cc][tid]; S = p.x; Sx = p.y; Sy = p.z; }
        block_sum3(S, Sx, Sy);
        if (tid == 0) {
            float ax = Sx / S, ay = Sy / S;
            s_ay2[cc] = ay;
            if (b == 0) { out[(9 + cc) * 2 + 0] = ax; out[(9 + cc) * 2 + 1] = ay; }
        }
        __syncthreads();
    }
    yA = s_ay2[0];                   // y9
    yB = s_ay2[1];                   // y10
    dis = __fsub_rn(yB, yA);         // dis0

    // ---------------- Band phases i = 8 .. 0 (one grid barrier each) ----------------
    for (int i = 8; i >= 0; i--) {
        if (tid == 0) {
            // scalar band logic; __f*_rn blocks FMA contraction to match reference
            float y1 = yA, y2 = yB;
            float last_y = floorf(y1);
            float tmp = ceilf(__fsub_rn(y2, y1));
            if (fabsf(__fsub_rn(tmp, dis)) > __fmul_rn(0.35f, dis)) {
                dsum = __fadd_rn(dsum, tmp);
                dnum = __fadd_rn(dnum, 1.0f);
                dis  = __fdiv_rn(dsum, fmaxf(dnum, 1.0f));
            }
            float t  = __fmul_rn(1.8f, dis);
            float sr = __fsub_rn(last_y, t);
            float end_y   = rintf(__fadd_rn(sr, t));   // round-half-even = jnp.round
            float start_y = rintf(sr);
            s_r0 = (start_y <= 0.f) ? 0  : (start_y >= (float)HH       ? HH     : (int)start_y);
            s_r1 = (end_y   <  0.f) ? -1 : (end_y   >= (float)(HH - 1) ? HH - 1 : (int)end_y);
        }
        __syncthreads();
        const int r0 = s_r0, r1 = s_r1;

        // Per-thread partial over this block's band rows: row-batched rescale,
        // then 4 unconditional expf (underflow to 0 is exact enough).
        float Mt = neg_inf(), S = 0.f, Sx = 0.f, Sy = 0.f;
        for (int row = r0 + b; row <= r1; row += NB) {
            if (tid < 512) {
                const float4 *rp = reinterpret_cast<const float4*>(hm + ((size_t)i * HH + row) * WW);
                float4 A = rp[tid];
                float v0 = A.x * 100.f, v1 = A.y * 100.f, v2 = A.z * 100.f, v3 = A.w * 100.f;
                float mr = fmaxf(fmaxf(v0, v1), fmaxf(v2, v3));
                if (mr > Mt) {
                    float r = expf(Mt - mr);   // expf(-inf)=0 on first row
                    S *= r; Sx *= r; Sy *= r;
                    Mt = mr;
                }
                float e0 = expf(v0 - Mt), e1 = expf(v1 - Mt), e2 = expf(v2 - Mt), e3 = expf(v3 - Mt);
                float es = (e0 + e1) + (e2 + e3);
                float x0 = (float)(tid << 2);
                S  += es;
                Sx += x0 * e0 + (x0 + 1.f) * e1 + (x0 + 2.f) * e2 + (x0 + 3.f) * e3;
                Sy += (float)row * es;
            }
        }
        // two-step block reduce: max, scale once, plain sums
        float Mb = block_max_bcast(Mt);
        float e = (Mt == neg_inf()) ? 0.f : expf(Mt - Mb);
        S *= e; Sx *= e; Sy *= e;
        block_sum3(S, Sx, Sy);
        const int bi = (8 - i) & 1;   // double-buffer by band parity
        if (tid == 0) g_bpart[bi][b] = make_float4(Mb, S, Sx, Sy);
        gsync(epoch, base);

        // finisher (redundant in every block): two-step over NB partials + closed-form tail
        float mi = neg_inf();
        float pS = 0.f, pSx = 0.f, pSy = 0.f;
        if (tid < NB) {
            float4 p = g_bpart[bi][tid];
            mi = p.x; pS = p.y; pSx = p.z; pSy = p.w;
        }
        float M = block_max_bcast(mi);
        float ee = (mi == neg_inf()) ? 0.f : expf(mi - M);
        pS *= ee; pSx *= ee; pSy *= ee;
        block_sum3(pS, pSx, pSy);
        if (tid == 0) {
            float Rn = (r1 >= r0) ? (float)(r1 - r0 + 1) : 0.f;
            float mb = M;
            float m;
            if (Rn >= 2048.f)      m = mb;
            else if (Rn > 0.f)     m = fmaxf(mb, 0.f);
            else                   m = 0.f;
            float sc = (Rn > 0.f) ? expf(mb - m) : 0.f;
            float S2 = pS * sc, Sx2 = pSx * sc, Sy2 = pSy * sc;

            if (Rn < 2048.f) {
                const float NTOT  = 4194304.f;      // H*W
                const float SXROW = 2096128.f;      // W*(W-1)/2
                const float SXTOT = 4292870144.f;   // H * SXROW
                const float SYTOT = 4292870144.f;   // W * H*(H-1)/2
                float e0 = expf(-m);
                S2  += (NTOT  - Rn * 2048.f) * e0;
                Sx2 += (SXTOT - Rn * SXROW ) * e0;
                Sy2 += (SYTOT - 2048.f * (0.5f * (float)(r0 + r1) * Rn)) * e0;
            }
            float ax = Sx2 / S2, ay = Sy2 / S2;
            s_ay = ay;
            if (b == 0) { out[i * 2 + 0] = ax; out[i * 2 + 1] = ay; }
        }
        __syncthreads();
        yB = yA;
        yA = s_ay;
    }
}

extern "C" void kernel_launch(void* const* d_in, const int* in_sizes, int n_in,
                              void* d_out, int out_size) {
    const float *hm = (const float*)d_in[0];
    float *out = (float*)d_out;
    (void)in_sizes; (void)n_in; (void)out_size;

    sa_kernel<<<NB, NT>>>(hm, out);
}

// round 7
// speedup vs baseline: 1.7653x; 1.2312x over previous
#include <cuda_runtime.h>

#define HH 2048
#define WW 2048
#define NB 148
#define NT 1024
#define NW (NT/32)
#define CBLK 74
#define TOT4 (HH*WW/4)          // 1,048,576 float4 per channel
#define STR (CBLK*NT)           // 75,776
#define SUB 16                  // band subgroup size
#define EPT 12                  // epochs per launch: 1 pass1 + 1 pass2 + 9 bands + 1 final

// Scratch (device globals; no allocation allowed)
// slots 0,1: band double-buffer (first SUB entries); 2,3: pass1 maxima; 4,5: pass2 sums
__device__ float4 g_bpart[6][NB];
__device__ unsigned g_flag[NB];          // per-block monotone epoch flags (+EPT per launch)

__device__ __forceinline__ float neg_inf() { return __int_as_float(0xff800000); }

// Block-wide max, broadcast to ALL threads.
__device__ float block_max_bcast(float m) {
    __shared__ float sm[NW];
    __shared__ float sM;
    int tid = threadIdx.x;
    __syncthreads();                       // protect smem reuse across calls
    #pragma unroll
    for (int o = 16; o; o >>= 1) m = fmaxf(m, __shfl_xor_sync(0xffffffffu, m, o));
    if ((tid & 31) == 0) sm[tid >> 5] = m;
    __syncthreads();
    if (tid < 32) {                        // NW == 32 exactly
        float t = sm[tid];
        #pragma unroll
        for (int o = 16; o; o >>= 1) t = fmaxf(t, __shfl_xor_sync(0xffffffffu, t, o));
        if (tid == 0) sM = t;
    }
    __syncthreads();
    return sM;
}

// Block-wide 3-way sum; result valid on threads 0..31.
__device__ void block_sum3(float &S, float &Sx, float &Sy) {
    __shared__ float ss[NW][3];
    int tid = threadIdx.x;
    __syncthreads();                       // protect smem reuse across calls
    #pragma unroll
    for (int o = 16; o; o >>= 1) {
        S  += __shfl_xor_sync(0xffffffffu, S, o);
        Sx += __shfl_xor_sync(0xffffffffu, Sx, o);
        Sy += __shfl_xor_sync(0xffffffffu, Sy, o);
    }
    if ((tid & 31) == 0) { ss[tid >> 5][0] = S; ss[tid >> 5][1] = Sx; ss[tid >> 5][2] = Sy; }
    __syncthreads();
    if (tid < 32) {
        S = ss[tid][0]; Sx = ss[tid][1]; Sy = ss[tid][2];
        #pragma unroll
        for (int o = 16; o; o >>= 1) {
            S  += __shfl_xor_sync(0xffffffffu, S, o);
            Sx += __shfl_xor_sync(0xffffffffu, Sx, o);
            Sy += __shfl_xor_sync(0xffffffffu, Sy, o);
        }
    }
}

// Fixed-max accumulate for phase0 pass 2. Ms is the SCALED (x100) global max.
__device__ __forceinline__ void accf(float Ms, float &S, float &Sx, float &Sy,
                                     float raw, float x, float y) {
    float v = raw * 100.f;
    if (v > Ms - 88.f) {
        float e = expf(v - Ms);
        S += e; Sx += x * e; Sy += y * e;
    }
}

// Publish this block's epoch (call after __threadfence + from tid 0 context).
__device__ __forceinline__ void flag_set(int b, unsigned v) {
    *(volatile unsigned*)&g_flag[b] = v;
}

// Poll the first n flags for >= target, with the first n threads in parallel.
__device__ __forceinline__ void flag_wait(int n, unsigned target) {
    int tid = threadIdx.x;
    if (tid < n) {
        while (*(volatile unsigned*)&g_flag[tid] < target) {}
    }
    __syncthreads();
    __threadfence();
}

__device__ __forceinline__ float fmax4(float4 A) {
    return fmaxf(fmaxf(A.x, A.y), fmaxf(A.z, A.w));
}

__global__ void __launch_bounds__(NT, 1)
sa_kernel(const float * __restrict__ hm, float * __restrict__ out) {
    const int b = blockIdx.x;
    const int tid = threadIdx.x;
    __shared__ unsigned s_base;
    __shared__ int s_r0, s_r1;
    __shared__ float s_ay;
    __shared__ float s_ay2[2];

    if (tid == 0) s_base = *(volatile unsigned*)&g_flag[b];   // own flag: stable base
    __syncthreads();
    const unsigned base = s_base;

    const int c  = (b < CBLK) ? 0 : 1;
    const int bb = (b < CBLK) ? b : b - CBLK;
    const float4 *p4 = reinterpret_cast<const float4*>(hm + (size_t)(9 + c) * HH * WW);
    const int ibase = bb * NT + tid;

    // ------------- Phase 0 / pass 1: branch-free RAW max, tile maxima kept in regs -------------
    float bmx[4];
    {
        #pragma unroll
        for (int k = 0; k < 3; k++) {
            float4 A = p4[ibase + (4*k + 0) * STR];
            float4 B = p4[ibase + (4*k + 1) * STR];
            float4 C = p4[ibase + (4*k + 2) * STR];
            float4 D = p4[ibase + (4*k + 3) * STR];
            bmx[k] = fmaxf(fmaxf(fmax4(A), fmax4(B)), fmaxf(fmax4(C), fmax4(D)));
        }
        float4 A = p4[ibase + 12 * STR];
        float m3 = fmax4(A);
        int i13 = ibase + 13 * STR;
        if (i13 < TOT4) { float4 B = p4[i13]; m3 = fmaxf(m3, fmax4(B)); }
        bmx[3] = m3;
        float m = block_max_bcast(fmaxf(fmaxf(bmx[0], bmx[1]), fmaxf(bmx[2], bmx[3])));
        if (tid == 0) {
            g_bpart[2 + c][bb] = make_float4(m, 0.f, 0.f, 0.f);  // RAW max
            __threadfence();
            flag_set(b, base + 1);
        }
    }
    flag_wait(NB, base + 1);            // full barrier (all-poll, no release)

    // This block's channel RAW global max (identical in all blocks of same channel).
    float Mraw;
    {
        float m = (tid < CBLK) ? g_bpart[2 + c][tid].x : neg_inf();
        Mraw = block_max_bcast(m);
    }

    // ---------- Phase 0 / pass 2: ballot-skip resum (L2 hits on the rare reloads) ----------
    {
        const float Ms     = Mraw * 100.f;      // scaled max used in exp
        const float thrRaw = Mraw - 0.88f;      // raw-domain skip threshold
        float S = 0.f, Sx = 0.f, Sy = 0.f;
        #pragma unroll
        for (int k = 0; k < 4; k++) {
            if (__any_sync(0xffffffffu, bmx[k] > thrRaw)) {
                int tlo = 4 * k, thi = (k == 3) ? 14 : 4 * k + 4;
                for (int t = tlo; t < thi; t++) {
                    int idx = ibase + t * STR;
                    if (idx < TOT4) {
                        float4 A = p4[idx];
                        float y  = (float)(idx >> 9);
                        float x0 = (float)((idx & 511) << 2);
                        accf(Ms, S, Sx, Sy, A.x, x0,       y);
                        accf(Ms, S, Sx, Sy, A.y, x0 + 1.f, y);
                        accf(Ms, S, Sx, Sy, A.z, x0 + 2.f, y);
                        accf(Ms, S, Sx, Sy, A.w, x0 + 3.f, y);
                    }
                }
            }
        }
        block_sum3(S, Sx, Sy);
        if (tid == 0) {
            g_bpart[4 + c][bb] = make_float4(S, Sx, Sy, 0.f);
            __threadfence();
        }
        __syncthreads();
    }

    // ---------------- Non-subgroup blocks: fast-forward epoch and exit ----------------
    if (b >= SUB) {
        if (tid == 0) flag_set(b, base + EPT);
        return;
    }
    if (tid == 0) flag_set(b, base + 2);
    flag_wait(NB, base + 2);            // gather: wait for all 148 pass-2 partials

    // ---------- Phase 0 finisher: each subgroup block computes y9,y10 redundantly ----------
    float yA, yB;
    float dis, dsum = 0.f, dnum = 0.f;
    for (int cc = 0; cc < 2; cc++) {
        float S = 0.f, Sx = 0.f, Sy = 0.f;
        if (tid < CBLK) { float4 p = g_bpart[4 + cc][tid]; S = p.x; Sx = p.y; Sy = p.z; }
        block_sum3(S, Sx, Sy);
        if (tid == 0) {
            float ax = Sx / S, ay = Sy / S;
            s_ay2[cc] = ay;
            if (b == 0) { out[(9 + cc) * 2 + 0] = ax; out[(9 + cc) * 2 + 1] = ay; }
        }
        __syncthreads();
    }
    yA = s_ay2[0];                   // y9
    yB = s_ay2[1];                   // y10
    dis = __fsub_rn(yB, yA);         // dis0

    // ---------------- Band phases i = 8 .. 0, entirely within the 16-block subgroup ----------------
    for (int i = 8; i >= 0; i--) {
        if (tid == 0) {
            // scalar band logic; __f*_rn blocks FMA contraction to match reference
            float y1 = yA, y2 = yB;
            float last_y = floorf(y1);
            float tmp = ceilf(__fsub_rn(y2, y1));
            if (fabsf(__fsub_rn(tmp, dis)) > __fmul_rn(0.35f, dis)) {
                dsum = __fadd_rn(dsum, tmp);
                dnum = __fadd_rn(dnum, 1.0f);
                dis  = __fdiv_rn(dsum, fmaxf(dnum, 1.0f));
            }
            float t  = __fmul_rn(1.8f, dis);
            float sr = __fsub_rn(last_y, t);
            float end_y   = rintf(__fadd_rn(sr, t));   // round-half-even = jnp.round
            float start_y = rintf(sr);
            s_r0 = (start_y <= 0.f) ? 0  : (start_y >= (float)HH       ? HH     : (int)start_y);
            s_r1 = (end_y   <  0.f) ? -1 : (end_y   >= (float)(HH - 1) ? HH - 1 : (int)end_y);
        }
        __syncthreads();
        const int r0 = s_r0, r1 = s_r1;

        // 2 rows per block pass (512 threads each), 32-row stride across 16 blocks.
        float Mt = neg_inf(), S = 0.f, Sx = 0.f, Sy = 0.f;
        {
            const int xt = tid & 511;
            const float x0 = (float)(xt << 2);
            for (int row = r0 + 2 * b + (tid >> 9); row <= r1; row += 2 * SUB) {
                const float4 *rp = reinterpret_cast<const float4*>(hm + ((size_t)i * HH + row) * WW);
                float4 A = rp[xt];
                float v0 = A.x * 100.f, v1 = A.y * 100.f, v2 = A.z * 100.f, v3 = A.w * 100.f;
                float mr = fmaxf(fmaxf(v0, v1), fmaxf(v2, v3));
                if (mr > Mt) {
                    float r = expf(Mt - mr);   // expf(-inf)=0 on first row
                    S *= r; Sx *= r; Sy *= r;
                    Mt = mr;
                }
                float e0 = expf(v0 - Mt), e1 = expf(v1 - Mt), e2 = expf(v2 - Mt), e3 = expf(v3 - Mt);
                float es = (e0 + e1) + (e2 + e3);
                S  += es;
                Sx += x0 * e0 + (x0 + 1.f) * e1 + (x0 + 2.f) * e2 + (x0 + 3.f) * e3;
                Sy += (float)row * es;
            }
        }
        // two-step block reduce: max, scale once, plain sums
        float Mb = block_max_bcast(Mt);
        float e = (Mt == neg_inf()) ? 0.f : expf(Mt - Mb);
        S *= e; Sx *= e; Sy *= e;
        block_sum3(S, Sx, Sy);
        const int bi = (8 - i) & 1;   // double-buffer by band parity
        if (tid == 0) {
            g_bpart[bi][b] = make_float4(Mb, S, Sx, Sy);
            __threadfence();
            flag_set(b, base + 3 + (8 - i));
        }
        flag_wait(SUB, base + 3 + (8 - i));   // mini-barrier among 16 blocks

        // finisher (redundant in every subgroup block): 16 partials + closed-form tail
        float mi = neg_inf();
        float pS = 0.f, pSx = 0.f, pSy = 0.f;
        if (tid < SUB) {
            float4 p = g_bpart[bi][tid];
            mi = p.x; pS = p.y; pSx = p.z; pSy = p.w;
        }
        float M = block_max_bcast(mi);
        float ee = (mi == neg_inf()) ? 0.f : expf(mi - M);
        pS *= ee; pSx *= ee; pSy *= ee;
        block_sum3(pS, pSx, pSy);
        if (tid == 0) {
            float Rn = (r1 >= r0) ? (float)(r1 - r0 + 1) : 0.f;
            float mb = M;
            float m;
            if (Rn >= 2048.f)      m = mb;
            else if (Rn > 0.f)     m = fmaxf(mb, 0.f);
            else                   m = 0.f;
            float sc = (Rn > 0.f) ? expf(mb - m) : 0.f;
            float S2 = pS * sc, Sx2 = pSx * sc, Sy2 = pSy * sc;

            if (Rn < 2048.f) {
                const float NTOT  = 4194304.f;      // H*W
                const float SXROW = 2096128.f;      // W*(W-1)/2
                const float SXTOT = 4292870144.f;   // H * SXROW
                const float SYTOT = 4292870144.f;   // W * H*(H-1)/2
                float e0 = expf(-m);
                S2  += (NTOT  - Rn * 2048.f) * e0;
                Sx2 += (SXTOT - Rn * SXROW ) * e0;
                Sy2 += (SYTOT - 2048.f * (0.5f * (float)(r0 + r1) * Rn)) * e0;
            }
            float ax = Sx2 / S2, ay = Sy2 / S2;
            s_ay = ay;
            if (b == 0) { out[i * 2 + 0] = ax; out[i * 2 + 1] = ay; }
        }
        __syncthreads();
        yB = yA;
        yA = s_ay;
    }

    // restore the uniform +EPT-per-launch flag invariant
    if (tid == 0) flag_set(b, base + EPT);
}

extern "C" void kernel_launch(void* const* d_in, const int* in_sizes, int n_in,
                              void* d_out, int out_size) {
    const float *hm = (const float*)d_in[0];
    float *out = (float*)d_out;
    (void)in_sizes; (void)n_in; (void)out_size;

    sa_kernel<<<NB, NT>>>(hm, out);
}

// round 9
// speedup vs baseline: 1.7765x; 1.0064x over previous
#include <cuda_runtime.h>

#define HH 2048
#define WW 2048
#define NB 148
#define NT 1024
#define NW 32
#define CBLK 74
#define TOT4 (HH*WW/4)          // 1,048,576 float4 per channel
#define STR (CBLK*NT)           // 75,776
#define SUB 32                  // band subgroup size
#define EPT 12                  // epochs per launch: pass1 + pass2 + 9 bands (+ headroom)

// Scratch (device globals; no allocation allowed)
// slots 0,1: band double-buffer (first SUB entries); 2,3: pass1 maxima; 4,5: pass2 sums
__device__ float4 g_part[6][NB];
__device__ unsigned g_flag[NB];          // per-block monotone epoch flags (+EPT per launch)

__device__ __forceinline__ float neg_inf() { return __int_as_float(0xff800000); }
__device__ __forceinline__ float fmax4(float4 A) {
    return fmaxf(fmaxf(A.x, A.y), fmaxf(A.z, A.w));
}

// Block-wide max, broadcast to ALL threads.
__device__ float block_max_bcast(float m) {
    __shared__ float sm[NW];
    __shared__ float sM;
    int tid = threadIdx.x;
    __syncthreads();                       // protect smem reuse across calls
    #pragma unroll
    for (int o = 16; o; o >>= 1) m = fmaxf(m, __shfl_xor_sync(0xffffffffu, m, o));
    if ((tid & 31) == 0) sm[tid >> 5] = m;
    __syncthreads();
    if (tid < 32) {
        float t = sm[tid];
        #pragma unroll
        for (int o = 16; o; o >>= 1) t = fmaxf(t, __shfl_xor_sync(0xffffffffu, t, o));
        if (tid == 0) sM = t;
    }
    __syncthreads();
    return sM;
}

// Block-wide 3-way sum; result valid on threads 0..31.
__device__ void block_sum3(float &S, float &Sx, float &Sy) {
    __shared__ float ss[NW][3];
    int tid = threadIdx.x;
    __syncthreads();                       // protect smem reuse across calls
    #pragma unroll
    for (int o = 16; o; o >>= 1) {
        S  += __shfl_xor_sync(0xffffffffu, S, o);
        Sx += __shfl_xor_sync(0xffffffffu, Sx, o);
        Sy += __shfl_xor_sync(0xffffffffu, Sy, o);
    }
    if ((tid & 31) == 0) { ss[tid >> 5][0] = S; ss[tid >> 5][1] = Sx; ss[tid >> 5][2] = Sy; }
    __syncthreads();
    if (tid < 32) {
        S = ss[tid][0]; Sx = ss[tid][1]; Sy = ss[tid][2];
        #pragma unroll
        for (int o = 16; o; o >>= 1) {
            S  += __shfl_xor_sync(0xffffffffu, S, o);
            Sx += __shfl_xor_sync(0xffffffffu, Sx, o);
            Sy += __shfl_xor_sync(0xffffffffu, Sy, o);
        }
    }
}

// Fixed-max accumulate for phase0 pass 2. Ms is the SCALED (x100) global max.
__device__ __forceinline__ void accf(float Ms, float &S, float &Sx, float &Sy,
                                     float raw, float x, float y) {
    float v = raw * 100.f;
    if (v > Ms - 88.f) {
        float e = expf(v - Ms);
        S += e; Sx += x * e; Sy += y * e;
    }
}

__device__ __forceinline__ void flag_set(int b, unsigned v) {
    *(volatile unsigned*)&g_flag[b] = v;
}

// Poll the first n flags for >= target, with the first n threads in parallel.
__device__ __forceinline__ void flag_wait(int n, unsigned target) {
    int tid = threadIdx.x;
    if (tid < n) {
        while (*(volatile unsigned*)&g_flag[tid] < target) {}
    }
    __syncthreads();
    __threadfence();
}

__global__ void __launch_bounds__(NT, 1)
sa_kernel(const float * __restrict__ hm, float * __restrict__ out) {
    const int b = blockIdx.x;
    const int tid = threadIdx.x;
    __shared__ unsigned s_base;
    __shared__ float s_ay, s_ay2[2];
    __shared__ float sMp[SUB], sSp[SUB], sSxp[SUB], sSyp[SUB];

    if (tid == 0) s_base = *(volatile unsigned*)&g_flag[b];   // own flag: +EPT per launch
    __syncthreads();
    const unsigned base = s_base;

    const int c  = (b < CBLK) ? 0 : 1;
    const int bb = (b < CBLK) ? b : b - CBLK;
    const float4 *p4 = reinterpret_cast<const float4*>(hm + (size_t)(9 + c) * HH * WW);
    const int ibase = bb * NT + tid;

    // ------------- Phase 0 / pass 1: branch-free RAW max, tile maxima kept in regs -------------
    float bmx[4];
    {
        #pragma unroll
        for (int k = 0; k < 3; k++) {
            float4 A = p4[ibase + (4*k + 0) * STR];
            float4 B = p4[ibase + (4*k + 1) * STR];
            float4 C = p4[ibase + (4*k + 2) * STR];
            float4 D = p4[ibase + (4*k + 3) * STR];
            bmx[k] = fmaxf(fmaxf(fmax4(A), fmax4(B)), fmaxf(fmax4(C), fmax4(D)));
        }
        float4 A = p4[ibase + 12 * STR];
        float m3 = fmax4(A);
        int i13 = ibase + 13 * STR;
        if (i13 < TOT4) { float4 B = p4[i13]; m3 = fmaxf(m3, fmax4(B)); }
        bmx[3] = m3;
        float m = block_max_bcast(fmaxf(fmaxf(bmx[0], bmx[1]), fmaxf(bmx[2], bmx[3])));
        if (tid == 0) {
            g_part[2 + c][bb] = make_float4(m, 0.f, 0.f, 0.f);  // RAW max
            __threadfence();
            flag_set(b, base + 1);
        }
    }
    flag_wait(NB, base + 1);            // full barrier (all-poll)

    // This block's channel RAW global max (identical in all blocks of same channel).
    float Mraw;
    {
        float m = (tid < CBLK) ? g_part[2 + c][tid].x : neg_inf();
        Mraw = block_max_bcast(m);
    }

    // ---------- Phase 0 / pass 2: ballot-skip resum (L2 hits on the rare reloads) ----------
    {
        const float Ms     = Mraw * 100.f;
        const float thrRaw = Mraw - 0.88f;
        float S = 0.f, Sx = 0.f, Sy = 0.f;
        #pragma unroll
        for (int k = 0; k < 4; k++) {
            if (__any_sync(0xffffffffu, bmx[k] > thrRaw)) {
                int tlo = 4 * k, thi = (k == 3) ? 14 : 4 * k + 4;
                for (int t = tlo; t < thi; t++) {
                    int idx = ibase + t * STR;
                    if (idx < TOT4) {
                        float4 A = p4[idx];
                        float y  = (float)(idx >> 9);
                        float x0 = (float)((idx & 511) << 2);
                        accf(Ms, S, Sx, Sy, A.x, x0,       y);
                        accf(Ms, S, Sx, Sy, A.y, x0 + 1.f, y);
                        accf(Ms, S, Sx, Sy, A.z, x0 + 2.f, y);
                        accf(Ms, S, Sx, Sy, A.w, x0 + 3.f, y);
                    }
                }
            }
        }
        block_sum3(S, Sx, Sy);
        if (tid == 0) {
            g_part[4 + c][bb] = make_float4(S, Sx, Sy, 0.f);
            __threadfence();
        }
        __syncthreads();
    }

    // ---------------- Non-subgroup blocks: fast-forward epoch and exit ----------------
    if (b >= SUB) {
        if (tid == 0) flag_set(b, base + EPT);
        return;
    }
    if (tid == 0) flag_set(b, base + 2);
    flag_wait(NB, base + 2);            // gather all 148 pass-2 partials

    // ---------- Phase 0 finisher: each subgroup block computes y9,y10 redundantly ----------
    for (int cc = 0; cc < 2; cc++) {
        float S = 0.f, Sx = 0.f, Sy = 0.f;
        if (tid < CBLK) { float4 p = g_part[4 + cc][tid]; S = p.x; Sx = p.y; Sy = p.z; }
        block_sum3(S, Sx, Sy);
        if (tid == 0) {
            float ax = Sx / S, ay = Sy / S;
            s_ay2[cc] = ay;
            if (b == 0) { out[(9 + cc) * 2 + 0] = ax; out[(9 + cc) * 2 + 1] = ay; }
        }
        __syncthreads();
    }
    // per-thread serial state (identical in every thread of every subgroup block)
    float yA = s_ay2[0], yB = s_ay2[1];
    float dis = __fsub_rn(yB, yA), dsum = 0.f, dnum = 0.f;

    // ---------------- Band phases i = 8 .. 0 (one fence+flag hop each) ----------------
    for (int i = 8; i >= 0; i--) {
        // scalar band logic, computed redundantly by ALL threads;
        // __f*_rn blocks FMA contraction to match reference
        {
            float tmp = ceilf(__fsub_rn(yB, yA));
            if (fabsf(__fsub_rn(tmp, dis)) > __fmul_rn(0.35f, dis)) {
                dsum = __fadd_rn(dsum, tmp);
                dnum = __fadd_rn(dnum, 1.0f);
                dis  = __fdiv_rn(dsum, fmaxf(dnum, 1.0f));
            }
        }
        float last_y = floorf(yA);
        float t  = __fmul_rn(1.8f, dis);
        float sr = __fsub_rn(last_y, t);
        float end_y   = rintf(__fadd_rn(sr, t));   // round-half-even = jnp.round
        float start_y = rintf(sr);
        const int r0 = (start_y <= 0.f) ? 0  : (start_y >= (float)HH       ? HH     : (int)start_y);
        const int r1 = (end_y   <  0.f) ? -1 : (end_y   >= (float)(HH - 1) ? HH - 1 : (int)end_y);
        const int rows = r1 - r0 + 1;

        const int j  = 8 - i;
        const int bi = j & 1;                   // double-buffer by band parity
        const unsigned ptag = base + 3 + (unsigned)j;   // 3..11 < EPT

        float Mloc = neg_inf(), S = 0.f, Sx = 0.f, Sy = 0.f;
        if (rows <= SUB) {
            // ---- fast path: one row per block; two-step max -> conditional exp ----
            int row = r0 + b;
            bool act = (tid < 512) && (b < rows);
            float v0 = 0.f, v1 = 0.f, v2 = 0.f, v3 = 0.f, mt = neg_inf();
            if (act) {
                const float4 *rp = reinterpret_cast<const float4*>(hm + ((size_t)i * HH + row) * WW);
                float4 A = rp[tid];
                v0 = A.x * 100.f; v1 = A.y * 100.f; v2 = A.z * 100.f; v3 = A.w * 100.f;
                mt = fmaxf(fmaxf(v0, v1), fmaxf(v2, v3));
            }
            float Mb = block_max_bcast(mt);     // this block's row max (scaled)
            Mloc = Mb;
            if (__any_sync(0xffffffffu, mt > Mb - 88.f)) {
                if (act) {
                    float e0 = expf(v0 - Mb), e1 = expf(v1 - Mb);
                    float e2 = expf(v2 - Mb), e3 = expf(v3 - Mb);
                    float es = (e0 + e1) + (e2 + e3);
                    float x0 = (float)(tid << 2);
                    S  += es;
                    Sx += x0 * e0 + (x0 + 1.f) * e1 + (x0 + 2.f) * e2 + (x0 + 3.f) * e3;
                    Sy += (float)row * es;
                }
            }
            block_sum3(S, Sx, Sy);
        } else {
            // ---- slow path (wide band): online rescale per row ----
            float Mt = neg_inf();
            if (tid < 512) {
                const float x0 = (float)(tid << 2);
                for (int row = r0 + b; row <= r1; row += SUB) {
                    const float4 *rp = reinterpret_cast<const float4*>(hm + ((size_t)i * HH + row) * WW);
                    float4 A = rp[tid];
                    float v0 = A.x * 100.f, v1 = A.y * 100.f, v2 = A.z * 100.f, v3 = A.w * 100.f;
                    float mr = fmaxf(fmaxf(v0, v1), fmaxf(v2, v3));
                    if (mr > Mt) {
                        float r = expf(Mt - mr);   // expf(-inf)=0 on first row
                        S *= r; Sx *= r; Sy *= r;
                        Mt = mr;
                    }
                    float e0 = expf(v0 - Mt), e1 = expf(v1 - Mt), e2 = expf(v2 - Mt), e3 = expf(v3 - Mt);
                    float es = (e0 + e1) + (e2 + e3);
                    S  += es;
                    Sx += x0 * e0 + (x0 + 1.f) * e1 + (x0 + 2.f) * e2 + (x0 + 3.f) * e3;
                    Sy += (float)row * es;
                }
            }
            float Mb = block_max_bcast(Mt);
            float e = (Mt == neg_inf()) ? 0.f : expf(Mt - Mb);
            S *= e; Sx *= e; Sy *= e;
            Mloc = Mb;
            block_sum3(S, Sx, Sy);
        }
        if (tid == 0) {
            g_part[bi][b] = make_float4(Mloc, S, Sx, Sy);
            __threadfence();
            flag_set(b, ptag);
        }
        flag_wait(SUB, ptag);               // mini-barrier among 32 blocks

        // stage the 32 partials into smem, then single-warp finisher + closed-form tail
        if (tid < SUB) {
            float4 p = g_part[bi][tid];
            sMp[tid] = p.x; sSp[tid] = p.y; sSxp[tid] = p.z; sSyp[tid] = p.w;
        }
        __syncthreads();
        if (tid < 32) {
            float Mk = sMp[tid], S2 = sSp[tid], Sx2 = sSxp[tid], Sy2 = sSyp[tid];
            float Mb = Mk;
            #pragma unroll
            for (int o = 16; o; o >>= 1) Mb = fmaxf(Mb, __shfl_xor_sync(0xffffffffu, Mb, o));
            float e = (Mk == neg_inf()) ? 0.f : expf(Mk - Mb);
            S2 *= e; Sx2 *= e; Sy2 *= e;
            #pragma unroll
            for (int o = 16; o; o >>= 1) {
                S2  += __shfl_xor_sync(0xffffffffu, S2, o);
                Sx2 += __shfl_xor_sync(0xffffffffu, Sx2, o);
                Sy2 += __shfl_xor_sync(0xffffffffu, Sy2, o);
            }
            if (tid == 0) {
                float Rn = (rows > 0) ? (float)rows : 0.f;
                float m;
                if (Rn >= 2048.f)      m = Mb;               // band covers everything
                else if (Rn > 0.f)     m = fmaxf(Mb, 0.f);   // zeros exist outside band
                else                   m = 0.f;              // empty band: all-zero map
                float sc = (Rn > 0.f) ? expf(Mb - m) : 0.f;
                S2 *= sc; Sx2 *= sc; Sy2 *= sc;
                if (Rn < 2048.f) {
                    const float NTOT  = 4194304.f;      // H*W
                    const float SXROW = 2096128.f;      // W*(W-1)/2
                    const float SXTOT = 4292870144.f;   // H * SXROW
                    const float SYTOT = 4292870144.f;   // W * H*(H-1)/2
                    float e0 = expf(-m);
                    S2  += (NTOT  - Rn * 2048.f) * e0;
                    Sx2 += (SXTOT - Rn * SXROW ) * e0;
                    Sy2 += (SYTOT - 2048.f * (0.5f * (float)(r0 + r1) * Rn)) * e0;
                }
                float ax = Sx2 / S2, ay = Sy2 / S2;
                s_ay = ay;
                if (b == 0) { out[i * 2 + 0] = ax; out[i * 2 + 1] = ay; }
            }
        }
        __syncthreads();
        yB = yA;
        yA = s_ay;
    }

    // restore the uniform +EPT-per-launch flag invariant
    if (tid == 0) flag_set(b, base + EPT);
}

extern "C" void kernel_launch(void* const* d_in, const int* in_sizes, int n_in,
                              void* d_out, int out_size) {
    const float *hm = (const float*)d_in[0];
    float *out = (float*)d_out;
    (void)in_sizes; (void)n_in; (void)out_size;

    sa_kernel<<<NB, NT>>>(hm, out);
}